// round 1
// baseline (speedup 1.0000x reference)
#include <cuda_runtime.h>
#include <cuda_bf16.h>

#define NN   512
#define NCH  20
#define H1   128
#define NB   32
#define NC   16

// Scratch (no allocations allowed)
__device__ float g_h[NN * NCH];          // hidden features (512 x 20)
__device__ float g_M[NB * NN * NC];      // M in [b][j][c] layout (32 x 512 x 16)
__device__ float g_o[NN * NB];           // minibatch features (512 x 32)

// ---------------------------------------------------------------------------
// K1: per-row MLP + projection to M.  grid=512 (one CTA per sample row),
// block=128.  All weights read through L2 (tiny).
// ---------------------------------------------------------------------------
__global__ void __launch_bounds__(128) k1_mlp_proj(
    const float* __restrict__ x,  const float* __restrict__ W1,
    const float* __restrict__ b1, const float* __restrict__ W2,
    const float* __restrict__ b2, const float* __restrict__ T)
{
    const int i = blockIdx.x;
    const int t = threadIdx.x;

    __shared__ float xs[NCH];
    __shared__ float h1s[H1];
    __shared__ float hs[NCH];

    if (t < NCH) xs[t] = x[i * NCH + t];
    __syncthreads();

    // fc1 + relu: thread t owns h1[t]
    float a = b1[t];
#pragma unroll
    for (int k = 0; k < NCH; ++k)
        a = fmaf(xs[k], W1[k * H1 + t], a);
    h1s[t] = fmaxf(a, 0.0f);
    __syncthreads();

    // fc2 + relu: threads 0..19 own h[c]
    if (t < NCH) {
        float c = b2[t];
#pragma unroll 8
        for (int k = 0; k < H1; ++k)
            c = fmaf(h1s[k], W2[k * NCH + t], c);
        c = fmaxf(c, 0.0f);
        hs[t] = c;
        g_h[i * NCH + t] = c;
    }
    __syncthreads();

    // M = h @ T  (20 -> 512), write into [b][i][c] layout
#pragma unroll
    for (int r = 0; r < 4; ++r) {
        const int col = t + r * 128;
        float m = 0.0f;
#pragma unroll
        for (int k = 0; k < NCH; ++k)
            m = fmaf(hs[k], T[k * NN + col], m);
        const int b = col >> 4;
        const int c = col & 15;
        g_M[(b * NN + i) * NC + c] = m;
    }
}

// ---------------------------------------------------------------------------
// K2: pairwise L1 + exp.  grid = 32 blocks * 4 i-chunks = 128 CTAs, block=128.
// Each CTA stages the full 512x16 block (32 KB) in smem; each thread owns one
// i-row in registers and sweeps all 512 j with broadcast shared loads.
// ---------------------------------------------------------------------------
__global__ void __launch_bounds__(128) k2_pairwise()
{
    const int b     = blockIdx.x >> 2;
    const int chunk = blockIdx.x & 3;
    const int t     = threadIdx.x;

    __shared__ float Mb[NN * NC];   // 32 KB

    // cooperative contiguous load (float4, coalesced)
    {
        const float4* src = reinterpret_cast<const float4*>(g_M + b * NN * NC);
        float4*       dst = reinterpret_cast<float4*>(Mb);
#pragma unroll
        for (int k = t; k < NN * NC / 4; k += 128)
            dst[k] = src[k];
    }
    __syncthreads();

    const int i = chunk * 128 + t;
    float mi[NC];
#pragma unroll
    for (int c = 0; c < NC; ++c) mi[c] = Mb[i * NC + c];

    float oacc = 0.0f;
    for (int j = 0; j < NN; ++j) {
        const float* __restrict__ mj = Mb + j * NC;
        float d0 = 0.f, d1 = 0.f, d2 = 0.f, d3 = 0.f;
#pragma unroll
        for (int c = 0; c < 4; ++c) {
            d0 += fabsf(mi[4 * c + 0] - mj[4 * c + 0]);
            d1 += fabsf(mi[4 * c + 1] - mj[4 * c + 1]);
            d2 += fabsf(mi[4 * c + 2] - mj[4 * c + 2]);
            d3 += fabsf(mi[4 * c + 3] - mj[4 * c + 3]);
        }
        const float d = (d0 + d1) + (d2 + d3);
        oacc += __expf(-d);
    }
    g_o[i * NB + b] = oacc;
}

// ---------------------------------------------------------------------------
// K3: deterministic mean reduction + final linear + sigmoid.
// Single CTA, 512 threads (one per output row).
// ---------------------------------------------------------------------------
__global__ void __launch_bounds__(512) k3_head(
    const float* __restrict__ W3, const float* __restrict__ b3,
    float* __restrict__ out)
{
    const int i = threadIdx.x;
    __shared__ float red[NN];

    float orow[NB];
    float s = 0.0f;
#pragma unroll
    for (int b = 0; b < NB; ++b) {
        orow[b] = g_o[i * NB + b];
        s += orow[b];
    }
    red[i] = s;
    __syncthreads();

#pragma unroll
    for (int st = 256; st > 0; st >>= 1) {
        if (i < st) red[i] += red[i + st];
        __syncthreads();
    }
    const float mean = red[0] * (1.0f / (float)(NN * NB));

    float acc = b3[0];
#pragma unroll
    for (int c = 0; c < NCH; ++c)
        acc = fmaf(g_h[i * NCH + c], W3[c], acc);
#pragma unroll
    for (int b = 0; b < NB; ++b)
        acc = fmaf(orow[b] - mean, W3[NCH + b], acc);

    out[i] = 1.0f / (1.0f + __expf(-acc));
}

// ---------------------------------------------------------------------------
extern "C" void kernel_launch(void* const* d_in, const int* in_sizes, int n_in,
                              void* d_out, int out_size)
{
    const float* x  = (const float*)d_in[0];
    const float* W1 = (const float*)d_in[1];
    const float* b1 = (const float*)d_in[2];
    const float* W2 = (const float*)d_in[3];
    const float* b2 = (const float*)d_in[4];
    const float* T  = (const float*)d_in[5];
    const float* W3 = (const float*)d_in[6];
    const float* b3 = (const float*)d_in[7];
    float* out = (float*)d_out;

    k1_mlp_proj<<<NN, 128>>>(x, W1, b1, W2, b2, T);
    k2_pairwise<<<NB * 4, 128>>>();
    k3_head<<<1, NN>>>(W3, b3, out);
}